// round 5
// baseline (speedup 1.0000x reference)
#include <cuda_runtime.h>
#include <cstdint>

#define NN 100000
#define EE 1600000
#define NPART 98   // ceil(NN/1024)

// ---------------------------------------------------------------------------
// Static device scratch
// ---------------------------------------------------------------------------
__device__ __align__(256) float g_dinv[NN];
__device__ __align__(256) float g_xx [NN * 36];     // dinv * padded x
__device__ __align__(256) float g_p0 [NN * 36];     // agg
__device__ __align__(256) float g_a1 [NN * 336];    // relu(conv1)
__device__ __align__(256) float g_tt2[NN * 168];    // dinv * (a1@W2)
__device__ __align__(256) float g_p2 [NN * 168];
__device__ __align__(256) float g_tt3[NN * 84];
__device__ __align__(256) float g_p3 [NN * 84];
__device__ __align__(256) float g_tt4[NN * 42];
__device__ __align__(256) float g_p4 [NN * 42];
__device__ __align__(256) float g_a4s[NN * 42];     // dinv * relu(p4+b4)
__device__ __align__(256) float g_p5 [NN * 42];

__device__ __align__(256) int g_cnt[NN];
__device__ __align__(256) int g_cur[NN];
__device__ __align__(256) int g_off[NN + 1];
__device__ __align__(256) int g_adj[EE];
__device__ __align__(256) int g_part[NPART];

// ---------------------------------------------------------------------------
// Packed f32x2 helpers (Blackwell FFMA2 — only via PTX)
// ---------------------------------------------------------------------------
__device__ __forceinline__ uint64_t pack2(float lo, float hi) {
    uint64_t r;
    asm("mov.b64 %0, {%1, %2};" : "=l"(r) : "f"(lo), "f"(hi));
    return r;
}
__device__ __forceinline__ void unpack2(uint64_t v, float& lo, float& hi) {
    asm("mov.b64 {%0, %1}, %2;" : "=f"(lo), "=f"(hi) : "l"(v));
}
__device__ __forceinline__ void ffma2(uint64_t& d, uint64_t a, uint64_t b) {
    asm("fma.rn.f32x2 %0, %1, %2, %3;" : "=l"(d) : "l"(a), "l"(b), "l"(d));
}

// ---------------------------------------------------------------------------
// CSR build
// ---------------------------------------------------------------------------
__global__ void k_zero2(int* cnt, int* cur) {
    int i = blockIdx.x * blockDim.x + threadIdx.x;
    if (i < NN) { cnt[i] = 0; cur[i] = 0; }
}
__global__ void k_count(const int* __restrict__ dst, int* cnt) {
    int e = blockIdx.x * blockDim.x + threadIdx.x;
    if (e < EE) atomicAdd(&cnt[dst[e]], 1);
}
__global__ void k_dinv(const int* __restrict__ cnt, float* __restrict__ dinv) {
    int i = blockIdx.x * blockDim.x + threadIdx.x;
    if (i < NN) dinv[i] = rsqrtf((float)cnt[i] + 1.0f);
}
__global__ void k_scan1(const int* __restrict__ cnt, int* __restrict__ off,
                        int* __restrict__ part) {
    __shared__ int s[1024];
    int t = threadIdx.x;
    int i = blockIdx.x * 1024 + t;
    int v = (i < NN) ? cnt[i] : 0;
    s[t] = v;
    __syncthreads();
    for (int d = 1; d < 1024; d <<= 1) {
        int u = (t >= d) ? s[t - d] : 0;
        __syncthreads();
        s[t] += u;
        __syncthreads();
    }
    if (i < NN) off[i] = s[t] - v;          // exclusive
    if (t == 1023) part[blockIdx.x] = s[1023];
}
__global__ void k_scan2(int* part, int* off) {
    if (threadIdx.x == 0 && blockIdx.x == 0) {
        int run = 0;
        for (int p = 0; p < NPART; p++) { int c = part[p]; part[p] = run; run += c; }
        off[NN] = EE;
    }
}
__global__ void k_scan3(int* __restrict__ off, const int* __restrict__ part) {
    int i = blockIdx.x * 1024 + threadIdx.x;
    if (i < NN) off[i] += part[blockIdx.x];
}
__global__ void k_fill(const int* __restrict__ src, const int* __restrict__ dst,
                       const int* __restrict__ off, int* cur, int* __restrict__ adj) {
    int e = blockIdx.x * blockDim.x + threadIdx.x;
    if (e >= EE) return;
    int d = dst[e];
    int p = off[d] + atomicAdd(&cur[d], 1);
    adj[p] = src[e];
}

// ---------------------------------------------------------------------------
// Elementwise fused kernels
// ---------------------------------------------------------------------------
__global__ void k_pad_scale(const float* __restrict__ x, const float* __restrict__ dinv,
                            float* __restrict__ xx) {
    int i = blockIdx.x * blockDim.x + threadIdx.x;
    if (i >= NN * 36) return;
    int n = i / 36, c = i - n * 36;
    float v = (c < 35) ? x[(size_t)n * 35 + c] : 0.0f;
    xx[i] = v * dinv[n];
}
__global__ void k_relu_bias_scale(const float* __restrict__ p4, const float* __restrict__ b4,
                                  const float* __restrict__ dinv, float* __restrict__ a4s) {
    int i = blockIdx.x * blockDim.x + threadIdx.x;
    if (i >= NN * 42) return;
    int n = i / 42;
    a4s[i] = fmaxf(p4[i] + b4[i % 42], 0.0f) * dinv[n];
}

// ---------------------------------------------------------------------------
// CSR gather aggregation, 2-way unrolled for MLP:
//   p[d] = dinv[d] * (tt[d] + sum_{s in N(d)} tt[s])
// ---------------------------------------------------------------------------
template <int D, int VEC>
__global__ void __launch_bounds__(252)
k_agg(const int* __restrict__ off, const int* __restrict__ adj,
      const float* __restrict__ dinv, const float* __restrict__ tt,
      float* __restrict__ p) {
    constexpr int G = D / VEC;
    constexpr int NPB = 252 / G;
    int g = threadIdx.x / G;
    int c = (threadIdx.x - g * G) * VEC;
    int node = blockIdx.x * NPB + g;
    if (node >= NN) return;
    int ib = off[node], ie = off[node + 1];
    if (VEC == 4) {
        float4 acc = *(const float4*)(tt + (size_t)node * D + c);
        float4 acc2 = make_float4(0.f, 0.f, 0.f, 0.f);
        int i = ib;
        for (; i + 2 <= ie; i += 2) {
            int s0 = adj[i], s1 = adj[i + 1];
            float4 v0 = *(const float4*)(tt + (size_t)s0 * D + c);
            float4 v1 = *(const float4*)(tt + (size_t)s1 * D + c);
            acc.x += v0.x; acc.y += v0.y; acc.z += v0.z; acc.w += v0.w;
            acc2.x += v1.x; acc2.y += v1.y; acc2.z += v1.z; acc2.w += v1.w;
        }
        if (i < ie) {
            int s0 = adj[i];
            float4 v0 = *(const float4*)(tt + (size_t)s0 * D + c);
            acc.x += v0.x; acc.y += v0.y; acc.z += v0.z; acc.w += v0.w;
        }
        float sc = dinv[node];
        acc.x = (acc.x + acc2.x) * sc; acc.y = (acc.y + acc2.y) * sc;
        acc.z = (acc.z + acc2.z) * sc; acc.w = (acc.w + acc2.w) * sc;
        *(float4*)(p + (size_t)node * D + c) = acc;
    } else {
        float2 acc = *(const float2*)(tt + (size_t)node * D + c);
        float2 acc2 = make_float2(0.f, 0.f);
        int i = ib;
        for (; i + 2 <= ie; i += 2) {
            int s0 = adj[i], s1 = adj[i + 1];
            float2 v0 = *(const float2*)(tt + (size_t)s0 * D + c);
            float2 v1 = *(const float2*)(tt + (size_t)s1 * D + c);
            acc.x += v0.x; acc.y += v0.y;
            acc2.x += v1.x; acc2.y += v1.y;
        }
        if (i < ie) {
            int s0 = adj[i];
            float2 v0 = *(const float2*)(tt + (size_t)s0 * D + c);
            acc.x += v0.x; acc.y += v0.y;
        }
        float sc = dinv[node];
        acc.x = (acc.x + acc2.x) * sc;
        acc.y = (acc.y + acc2.y) * sc;
        *(float2*)(p + (size_t)node * D + c) = acc;
    }
}

// ---------------------------------------------------------------------------
// f32x2 GEMM, 128x64 tile, 256 threads, 8x4 microtile (used for Nd < 128).
// As stride 130 (even) -> ulonglong2 reads stay 16B-aligned.
// ---------------------------------------------------------------------------
template <bool IN_RELU, bool OUT_RELU, bool OUT_SCALE>
__global__ void __launch_bounds__(256)
k_gemm2(const float* __restrict__ A, int lda, const float* __restrict__ binA,
        const float* __restrict__ B, const float* __restrict__ bout,
        float* __restrict__ C, const float* __restrict__ dinv,
        int M, int K, int Nd) {
    __shared__ uint64_t As[16][130];
    __shared__ uint64_t Bs[16][34];

    int tid = threadIdx.x;
    int tx = tid & 15;
    int ty = tid >> 4;
    int row0 = blockIdx.x * 128;
    int col0 = blockIdx.y * 64;

    uint64_t acc[8][2];
#pragma unroll
    for (int i = 0; i < 8; i++) { acc[i][0] = 0ull; acc[i][1] = 0ull; }

    for (int k0 = 0; k0 < K; k0 += 16) {
#pragma unroll
        for (int l = 0; l < 8; l++) {
            int idx = tid + l * 256;
            int kk = idx & 15, rr = idx >> 4;
            int grow = row0 + rr, gk = k0 + kk;
            float a = 0.0f;
            if (grow < M && gk < K) {
                a = A[(size_t)grow * lda + gk];
                if (IN_RELU) a = fmaxf(a + binA[gk], 0.0f);
            }
            As[kk][rr] = pack2(a, a);
        }
#pragma unroll
        for (int l = 0; l < 2; l++) {
            int idx = tid + l * 256;
            int cp = idx & 31, kk = idx >> 5;
            int gk = k0 + kk, gc = col0 + 2 * cp;
            float2 bv = make_float2(0.0f, 0.0f);
            if (gk < K && gc < Nd) bv = *(const float2*)(B + (size_t)gk * Nd + gc);
            Bs[kk][cp] = pack2(bv.x, bv.y);
        }
        __syncthreads();
#pragma unroll
        for (int kk = 0; kk < 16; kk++) {
            ulonglong2 bb = *(const ulonglong2*)&Bs[kk][2 * tx];
#pragma unroll
            for (int i = 0; i < 4; i++) {
                ulonglong2 aa = *(const ulonglong2*)&As[kk][ty * 8 + 2 * i];
                ffma2(acc[2 * i][0],     aa.x, bb.x);
                ffma2(acc[2 * i][1],     aa.x, bb.y);
                ffma2(acc[2 * i + 1][0], aa.y, bb.x);
                ffma2(acc[2 * i + 1][1], aa.y, bb.y);
            }
        }
        __syncthreads();
    }

    int colb = col0 + tx * 4;
    bool fullvec = (row0 + 127 < M) && (col0 + 63 < Nd);
    if (fullvec) {
        float4 bb;
        if (OUT_RELU) bb = *(const float4*)(bout + colb);
#pragma unroll
        for (int i = 0; i < 8; i++) {
            int row = row0 + ty * 8 + i;
            float4 v;
            unpack2(acc[i][0], v.x, v.y);
            unpack2(acc[i][1], v.z, v.w);
            if (OUT_RELU) {
                v.x = fmaxf(v.x + bb.x, 0.f); v.y = fmaxf(v.y + bb.y, 0.f);
                v.z = fmaxf(v.z + bb.z, 0.f); v.w = fmaxf(v.w + bb.w, 0.f);
            }
            if (OUT_SCALE) {
                float s = dinv[row];
                v.x *= s; v.y *= s; v.z *= s; v.w *= s;
            }
            *(float4*)(C + (size_t)row * Nd + colb) = v;
        }
    } else {
#pragma unroll
        for (int i = 0; i < 8; i++) {
            int row = row0 + ty * 8 + i;
            if (row >= M) continue;
            float vv[4];
            unpack2(acc[i][0], vv[0], vv[1]);
            unpack2(acc[i][1], vv[2], vv[3]);
            float s = OUT_SCALE ? dinv[row] : 1.0f;
#pragma unroll
            for (int j = 0; j < 4; j++) {
                int col = colb + j;
                if (col >= Nd) continue;
                float v = vv[j];
                if (OUT_RELU) v = fmaxf(v + bout[col], 0.0f);
                if (OUT_SCALE) v *= s;
                C[(size_t)row * Nd + col] = v;
            }
        }
    }
}

// ---------------------------------------------------------------------------
// f32x2 GEMM, 128x128 tile, 256 threads, 8x8 microtile (Nd >= 128 layers).
// As stride 131 (odd): u64 stores land on 16 distinct bank groups
// (kk*131*2 mod 32 = kk*6 mod 32 is a permutation of evens over kk=0..15).
// A reads are 16-lane broadcasts done as TWO u64 LDS (8B-aligned; an
// ulonglong2 read here would be 8-mod-16 misaligned for odd kk).
// ---------------------------------------------------------------------------
template <bool IN_RELU, bool OUT_RELU, bool OUT_SCALE>
__global__ void __launch_bounds__(256, 2)
k_gemm3(const float* __restrict__ A, int lda, const float* __restrict__ binA,
        const float* __restrict__ B, const float* __restrict__ bout,
        float* __restrict__ C, const float* __restrict__ dinv,
        int M, int K, int Nd) {
    __shared__ uint64_t As[16][131];
    __shared__ uint64_t Bs2[16][4][34];

    int tid = threadIdx.x;
    int tx = tid & 15;
    int ty = tid >> 4;
    int row0 = blockIdx.x * 128;
    int col0 = blockIdx.y * 128;

    uint64_t acc[8][4];
#pragma unroll
    for (int i = 0; i < 8; i++)
#pragma unroll
        for (int j = 0; j < 4; j++) acc[i][j] = 0ull;

    for (int k0 = 0; k0 < K; k0 += 16) {
#pragma unroll
        for (int l = 0; l < 8; l++) {
            int idx = tid + l * 256;
            int kk = idx & 15, rr = idx >> 4;
            int grow = row0 + rr, gk = k0 + kk;
            float a = 0.0f;
            if (grow < M && gk < K) {
                a = A[(size_t)grow * lda + gk];
                if (IN_RELU) a = fmaxf(a + binA[gk], 0.0f);
            }
            As[kk][rr] = pack2(a, a);
        }
#pragma unroll
        for (int l = 0; l < 4; l++) {
            int idx = tid + l * 256;
            int cpl = idx & 63, kk = idx >> 6;
            int gk = k0 + kk, gc = col0 + 2 * cpl;
            float2 bv = make_float2(0.0f, 0.0f);
            if (gk < K && gc + 1 < Nd) bv = *(const float2*)(B + (size_t)gk * Nd + gc);
            else if (gk < K && gc < Nd) bv.x = B[(size_t)gk * Nd + gc];
            Bs2[kk][cpl >> 4][cpl & 15] = pack2(bv.x, bv.y);
        }
        __syncthreads();
#pragma unroll
        for (int kk = 0; kk < 16; kk++) {
            uint64_t bb[4];
#pragma unroll
            for (int j = 0; j < 4; j++) bb[j] = Bs2[kk][j][tx];
#pragma unroll
            for (int i = 0; i < 4; i++) {
                uint64_t a0 = As[kk][ty * 8 + 2 * i];
                uint64_t a1 = As[kk][ty * 8 + 2 * i + 1];
#pragma unroll
                for (int j = 0; j < 4; j++) {
                    ffma2(acc[2 * i][j],     a0, bb[j]);
                    ffma2(acc[2 * i + 1][j], a1, bb[j]);
                }
            }
        }
        __syncthreads();
    }

    bool fullvec = (row0 + 127 < M) && (col0 + 127 < Nd);
    if (fullvec) {
        float2 bb[4];
        if (OUT_RELU) {
#pragma unroll
            for (int j = 0; j < 4; j++)
                bb[j] = *(const float2*)(bout + col0 + j * 32 + 2 * tx);
        }
#pragma unroll
        for (int i = 0; i < 8; i++) {
            int row = row0 + ty * 8 + i;
            float s = OUT_SCALE ? dinv[row] : 1.0f;
#pragma unroll
            for (int j = 0; j < 4; j++) {
                float2 v;
                unpack2(acc[i][j], v.x, v.y);
                if (OUT_RELU) {
                    v.x = fmaxf(v.x + bb[j].x, 0.f);
                    v.y = fmaxf(v.y + bb[j].y, 0.f);
                }
                if (OUT_SCALE) { v.x *= s; v.y *= s; }
                *(float2*)(C + (size_t)row * Nd + col0 + j * 32 + 2 * tx) = v;
            }
        }
    } else {
#pragma unroll
        for (int i = 0; i < 8; i++) {
            int row = row0 + ty * 8 + i;
            if (row >= M) continue;
            float s = OUT_SCALE ? dinv[row] : 1.0f;
#pragma unroll
            for (int j = 0; j < 4; j++) {
                float lo, hi;
                unpack2(acc[i][j], lo, hi);
                int col = col0 + j * 32 + 2 * tx;
                if (col < Nd) {
                    float v = lo;
                    if (OUT_RELU) v = fmaxf(v + bout[col], 0.0f);
                    if (OUT_SCALE) v *= s;
                    C[(size_t)row * Nd + col] = v;
                }
                if (col + 1 < Nd) {
                    float v = hi;
                    if (OUT_RELU) v = fmaxf(v + bout[col + 1], 0.0f);
                    if (OUT_SCALE) v *= s;
                    C[(size_t)row * Nd + col + 1] = v;
                }
            }
        }
    }
}

// ---------------------------------------------------------------------------
// Final fused head: mu/logstd GEMV (42 -> 21 each), reparam, log_softmax.
// ---------------------------------------------------------------------------
__global__ void __launch_bounds__(128)
k_final(const float* __restrict__ p5,
        const float* __restrict__ Wmu, const float* __restrict__ bmu,
        const float* __restrict__ Wls, const float* __restrict__ bls,
        const float* __restrict__ eps, float* __restrict__ out) {
    __shared__ float sWmu[42 * 21];
    __shared__ float sWls[42 * 21];
    __shared__ float sbmu[21];
    __shared__ float sbls[21];
    for (int i = threadIdx.x; i < 42 * 21; i += blockDim.x) {
        sWmu[i] = Wmu[i];
        sWls[i] = Wls[i];
    }
    if (threadIdx.x < 21) {
        sbmu[threadIdx.x] = bmu[threadIdx.x];
        sbls[threadIdx.x] = bls[threadIdx.x];
    }
    __syncthreads();

    int n = blockIdx.x * blockDim.x + threadIdx.x;
    if (n >= NN) return;

    float xr[42];
#pragma unroll
    for (int i = 0; i < 42; i++) xr[i] = p5[(size_t)n * 42 + i];

    float z[21];
#pragma unroll
    for (int j = 0; j < 21; j++) {
        float mu = sbmu[j];
        float ls = sbls[j];
#pragma unroll
        for (int i = 0; i < 42; i++) {
            mu += xr[i] * sWmu[i * 21 + j];
            ls += xr[i] * sWls[i * 21 + j];
        }
        ls = fminf(ls, 10.0f);
        z[j] = mu + eps[(size_t)n * 21 + j] * expf(ls);
    }
    float m = z[0];
#pragma unroll
    for (int j = 1; j < 21; j++) m = fmaxf(m, z[j]);
    float s = 0.0f;
#pragma unroll
    for (int j = 0; j < 21; j++) s += expf(z[j] - m);
    float lse = m + logf(s);
#pragma unroll
    for (int j = 0; j < 21; j++) out[(size_t)n * 21 + j] = z[j] - lse;
}

// ---------------------------------------------------------------------------
static inline int cdiv(long a, long b) { return (int)((a + b - 1) / b); }

extern "C" void kernel_launch(void* const* d_in, const int* in_sizes, int n_in,
                              void* d_out, int out_size) {
    const float* x    = (const float*)d_in[0];
    const int*   ei   = (const int*)  d_in[1];
    const float* eps  = (const float*)d_in[2];
    const float* W1   = (const float*)d_in[3];
    const float* b1   = (const float*)d_in[4];
    const float* W2   = (const float*)d_in[5];
    const float* b2   = (const float*)d_in[6];
    const float* W3   = (const float*)d_in[7];
    const float* b3   = (const float*)d_in[8];
    const float* W4   = (const float*)d_in[9];
    const float* b4   = (const float*)d_in[10];
    const float* Wmu  = (const float*)d_in[11];
    const float* bmu  = (const float*)d_in[12];
    const float* Wls  = (const float*)d_in[13];
    const float* bls  = (const float*)d_in[14];
    float* out = (float*)d_out;

    float *dinv, *xx, *p0, *a1, *tt2, *p2, *tt3, *p3, *tt4, *p4, *a4s, *p5;
    int *cnt, *cur, *off, *adj, *part;
    cudaGetSymbolAddress((void**)&dinv, g_dinv);
    cudaGetSymbolAddress((void**)&xx,  g_xx);
    cudaGetSymbolAddress((void**)&p0,  g_p0);
    cudaGetSymbolAddress((void**)&a1,  g_a1);
    cudaGetSymbolAddress((void**)&tt2, g_tt2);
    cudaGetSymbolAddress((void**)&p2,  g_p2);
    cudaGetSymbolAddress((void**)&tt3, g_tt3);
    cudaGetSymbolAddress((void**)&p3,  g_p3);
    cudaGetSymbolAddress((void**)&tt4, g_tt4);
    cudaGetSymbolAddress((void**)&p4,  g_p4);
    cudaGetSymbolAddress((void**)&a4s, g_a4s);
    cudaGetSymbolAddress((void**)&p5,  g_p5);
    cudaGetSymbolAddress((void**)&cnt, g_cnt);
    cudaGetSymbolAddress((void**)&cur, g_cur);
    cudaGetSymbolAddress((void**)&off, g_off);
    cudaGetSymbolAddress((void**)&adj, g_adj);
    cudaGetSymbolAddress((void**)&part, g_part);

    const int* src = ei;
    const int* dst = ei + EE;

    // ---- CSR build + normalization ----
    k_zero2<<<cdiv(NN, 256), 256>>>(cnt, cur);
    k_count<<<cdiv(EE, 256), 256>>>(dst, cnt);
    k_dinv<<<cdiv(NN, 256), 256>>>(cnt, dinv);
    k_scan1<<<NPART, 1024>>>(cnt, off, part);
    k_scan2<<<1, 32>>>(part, off);
    k_scan3<<<NPART, 1024>>>(off, part);
    k_fill<<<cdiv(EE, 256), 256>>>(src, dst, off, cur, adj);

    // ---- conv1: aggregate x (D=36), then GEMM 35->336 (+b1, relu) ----
    k_pad_scale<<<cdiv((long)NN * 36, 256), 256>>>(x, dinv, xx);
    k_agg<36, 4><<<cdiv(NN, 28), 252>>>(off, adj, dinv, xx, p0);
    k_gemm3<false, true, false><<<dim3(cdiv(NN, 128), cdiv(336, 128)), 256>>>(
        p0, 36, nullptr, W1, b1, a1, nullptr, NN, 35, 336);

    // ---- conv2: GEMM 336->168 (scaled out), aggregate ----
    k_gemm3<false, false, true><<<dim3(cdiv(NN, 128), cdiv(168, 128)), 256>>>(
        a1, 336, nullptr, W2, nullptr, tt2, dinv, NN, 336, 168);
    k_agg<168, 4><<<cdiv(NN, 6), 252>>>(off, adj, dinv, tt2, p2);

    // ---- conv3: in = relu(p2+b2), 168->84, scaled out ----
    k_gemm2<true, false, true><<<dim3(cdiv(NN, 128), 2), 256>>>(
        p2, 168, b2, W3, nullptr, tt3, dinv, NN, 168, 84);
    k_agg<84, 4><<<cdiv(NN, 12), 252>>>(off, adj, dinv, tt3, p3);

    // ---- conv4: in = relu(p3+b3), 84->42, scaled out ----
    k_gemm2<true, false, true><<<dim3(cdiv(NN, 128), 1), 256>>>(
        p3, 84, b3, W4, nullptr, tt4, dinv, NN, 84, 42);
    k_agg<42, 2><<<cdiv(NN, 12), 252>>>(off, adj, dinv, tt4, p4);

    // ---- shared head propagation: a4s = dinv*relu(p4+b4), aggregate ----
    k_relu_bias_scale<<<cdiv((long)NN * 42, 256), 256>>>(p4, b4, dinv, a4s);
    k_agg<42, 2><<<cdiv(NN, 12), 252>>>(off, adj, dinv, a4s, p5);

    // ---- fused heads + reparam + log_softmax ----
    k_final<<<cdiv(NN, 128), 128>>>(p5, Wmu, bmu, Wls, bls, eps, out);
}

// round 6
// speedup vs baseline: 1.1490x; 1.1490x over previous
#include <cuda_runtime.h>
#include <cstdint>

#define NN 100000
#define EE 1600000
#define NPART 98   // ceil(NN/1024)

// ---------------------------------------------------------------------------
// Static device scratch
// ---------------------------------------------------------------------------
__device__ __align__(256) float g_dinv[NN];
__device__ __align__(256) float g_xx [NN * 36];     // dinv * padded x
__device__ __align__(256) float g_p0 [NN * 36];     // agg
__device__ __align__(256) float g_a1 [NN * 336];    // relu(conv1)
__device__ __align__(256) float g_tt2[NN * 168];    // dinv * (a1@W2)
__device__ __align__(256) float g_p2 [NN * 168];
__device__ __align__(256) float g_tt3[NN * 84];
__device__ __align__(256) float g_p3 [NN * 84];
__device__ __align__(256) float g_tt4[NN * 42];
__device__ __align__(256) float g_a4s[NN * 42];     // dinv * relu(p4+b4), fused in agg
__device__ __align__(256) float g_p5 [NN * 42];

__device__ __align__(256) int g_cnt[NN];
__device__ __align__(256) int g_cur[NN];
__device__ __align__(256) int g_off[NN + 1];
__device__ __align__(256) int g_adj[EE];
__device__ __align__(256) int g_part[NPART];

// ---------------------------------------------------------------------------
// Packed f32x2 helpers (Blackwell FFMA2 — only via PTX)
// ---------------------------------------------------------------------------
__device__ __forceinline__ uint64_t pack2(float lo, float hi) {
    uint64_t r;
    asm("mov.b64 %0, {%1, %2};" : "=l"(r) : "f"(lo), "f"(hi));
    return r;
}
__device__ __forceinline__ void unpack2(uint64_t v, float& lo, float& hi) {
    asm("mov.b64 {%0, %1}, %2;" : "=f"(lo), "=f"(hi) : "l"(v));
}
__device__ __forceinline__ void ffma2(uint64_t& d, uint64_t a, uint64_t b) {
    asm("fma.rn.f32x2 %0, %1, %2, %3;" : "=l"(d) : "l"(a), "l"(b), "l"(d));
}

// ---------------------------------------------------------------------------
// CSR build
// ---------------------------------------------------------------------------
__global__ void k_zero2(int* cnt, int* cur) {
    int i = blockIdx.x * blockDim.x + threadIdx.x;
    if (i < NN) { cnt[i] = 0; cur[i] = 0; }
}
__global__ void k_count(const int* __restrict__ dst, int* cnt) {
    int e = blockIdx.x * blockDim.x + threadIdx.x;
    if (e < EE) atomicAdd(&cnt[dst[e]], 1);
}
// scan1 also emits dinv = rsqrt(cnt+1)
__global__ void k_scan1(const int* __restrict__ cnt, int* __restrict__ off,
                        int* __restrict__ part, float* __restrict__ dinv) {
    __shared__ int s[1024];
    int t = threadIdx.x;
    int i = blockIdx.x * 1024 + t;
    int v = (i < NN) ? cnt[i] : 0;
    if (i < NN) dinv[i] = rsqrtf((float)v + 1.0f);
    s[t] = v;
    __syncthreads();
    for (int d = 1; d < 1024; d <<= 1) {
        int u = (t >= d) ? s[t - d] : 0;
        __syncthreads();
        s[t] += u;
        __syncthreads();
    }
    if (i < NN) off[i] = s[t] - v;          // exclusive
    if (t == 1023) part[blockIdx.x] = s[1023];
}
__global__ void k_scan2(int* part, int* off) {
    if (threadIdx.x == 0 && blockIdx.x == 0) {
        int run = 0;
        for (int p = 0; p < NPART; p++) { int c = part[p]; part[p] = run; run += c; }
        off[NN] = EE;
    }
}
__global__ void k_scan3(int* __restrict__ off, const int* __restrict__ part) {
    int i = blockIdx.x * 1024 + threadIdx.x;
    if (i < NN) off[i] += part[blockIdx.x];
}
__global__ void k_fill(const int* __restrict__ src, const int* __restrict__ dst,
                       const int* __restrict__ off, int* cur, int* __restrict__ adj) {
    int e = blockIdx.x * blockDim.x + threadIdx.x;
    if (e >= EE) return;
    int d = dst[e];
    int p = off[d] + atomicAdd(&cur[d], 1);
    adj[p] = src[e];
}

// ---------------------------------------------------------------------------
// Elementwise: xx = dinv[n] * pad(x)   (35 -> 36)
// ---------------------------------------------------------------------------
__global__ void k_pad_scale(const float* __restrict__ x, const float* __restrict__ dinv,
                            float* __restrict__ xx) {
    int i = blockIdx.x * blockDim.x + threadIdx.x;
    if (i >= NN * 36) return;
    int n = i / 36, c = i - n * 36;
    float v = (c < 35) ? x[(size_t)n * 35 + c] : 0.0f;
    xx[i] = v * dinv[n];
}

// ---------------------------------------------------------------------------
// CSR gather aggregation, 2-way unrolled (MLP=2):
//   base: p[d] = dinv[d] * (tt[d] + sum_{s in N(d)} tt[s])
//   RBS:  p[d] = dinv[d] * relu(base + bias[c])   (fused relu+bias+rescale)
// ---------------------------------------------------------------------------
template <int D, int VEC, bool RBS>
__global__ void __launch_bounds__(252)
k_agg(const int* __restrict__ off, const int* __restrict__ adj,
      const float* __restrict__ dinv, const float* __restrict__ tt,
      const float* __restrict__ bias, float* __restrict__ p) {
    constexpr int G = D / VEC;
    constexpr int NPB = 252 / G;
    int g = threadIdx.x / G;
    int c = (threadIdx.x - g * G) * VEC;
    int node = blockIdx.x * NPB + g;
    if (node >= NN) return;
    int ib = off[node], ie = off[node + 1];
    float sc = dinv[node];
    if (VEC == 4) {
        float4 acc = *(const float4*)(tt + (size_t)node * D + c);
        float4 acc2 = make_float4(0.f, 0.f, 0.f, 0.f);
        int i = ib;
        for (; i + 2 <= ie; i += 2) {
            int s0 = adj[i], s1 = adj[i + 1];
            float4 v0 = *(const float4*)(tt + (size_t)s0 * D + c);
            float4 v1 = *(const float4*)(tt + (size_t)s1 * D + c);
            acc.x += v0.x; acc.y += v0.y; acc.z += v0.z; acc.w += v0.w;
            acc2.x += v1.x; acc2.y += v1.y; acc2.z += v1.z; acc2.w += v1.w;
        }
        if (i < ie) {
            int s0 = adj[i];
            float4 v0 = *(const float4*)(tt + (size_t)s0 * D + c);
            acc.x += v0.x; acc.y += v0.y; acc.z += v0.z; acc.w += v0.w;
        }
        acc.x = (acc.x + acc2.x) * sc; acc.y = (acc.y + acc2.y) * sc;
        acc.z = (acc.z + acc2.z) * sc; acc.w = (acc.w + acc2.w) * sc;
        if (RBS) {
            acc.x = fmaxf(acc.x + bias[c + 0], 0.f) * sc;
            acc.y = fmaxf(acc.y + bias[c + 1], 0.f) * sc;
            acc.z = fmaxf(acc.z + bias[c + 2], 0.f) * sc;
            acc.w = fmaxf(acc.w + bias[c + 3], 0.f) * sc;
        }
        *(float4*)(p + (size_t)node * D + c) = acc;
    } else {
        float2 acc = *(const float2*)(tt + (size_t)node * D + c);
        float2 acc2 = make_float2(0.f, 0.f);
        int i = ib;
        for (; i + 2 <= ie; i += 2) {
            int s0 = adj[i], s1 = adj[i + 1];
            float2 v0 = *(const float2*)(tt + (size_t)s0 * D + c);
            float2 v1 = *(const float2*)(tt + (size_t)s1 * D + c);
            acc.x += v0.x; acc.y += v0.y;
            acc2.x += v1.x; acc2.y += v1.y;
        }
        if (i < ie) {
            int s0 = adj[i];
            float2 v0 = *(const float2*)(tt + (size_t)s0 * D + c);
            acc.x += v0.x; acc.y += v0.y;
        }
        acc.x = (acc.x + acc2.x) * sc;
        acc.y = (acc.y + acc2.y) * sc;
        if (RBS) {
            acc.x = fmaxf(acc.x + bias[c + 0], 0.f) * sc;
            acc.y = fmaxf(acc.y + bias[c + 1], 0.f) * sc;
        }
        *(float2*)(p + (size_t)node * D + c) = acc;
    }
}

// ---------------------------------------------------------------------------
// f32x2 GEMM, 128x64 tile, 256 threads, 8x4 microtile (R3-proven config).
// As stride 130 (even) -> ulonglong2 reads stay 16B-aligned.
// ---------------------------------------------------------------------------
template <bool IN_RELU, bool OUT_RELU, bool OUT_SCALE>
__global__ void __launch_bounds__(256)
k_gemm2(const float* __restrict__ A, int lda, const float* __restrict__ binA,
        const float* __restrict__ B, const float* __restrict__ bout,
        float* __restrict__ C, const float* __restrict__ dinv,
        int M, int K, int Nd) {
    __shared__ uint64_t As[16][130];
    __shared__ uint64_t Bs[16][34];

    int tid = threadIdx.x;
    int tx = tid & 15;
    int ty = tid >> 4;
    int row0 = blockIdx.x * 128;
    int col0 = blockIdx.y * 64;

    uint64_t acc[8][2];
#pragma unroll
    for (int i = 0; i < 8; i++) { acc[i][0] = 0ull; acc[i][1] = 0ull; }

    for (int k0 = 0; k0 < K; k0 += 16) {
#pragma unroll
        for (int l = 0; l < 8; l++) {
            int idx = tid + l * 256;
            int kk = idx & 15, rr = idx >> 4;
            int grow = row0 + rr, gk = k0 + kk;
            float a = 0.0f;
            if (grow < M && gk < K) {
                a = A[(size_t)grow * lda + gk];
                if (IN_RELU) a = fmaxf(a + binA[gk], 0.0f);
            }
            As[kk][rr] = pack2(a, a);
        }
#pragma unroll
        for (int l = 0; l < 2; l++) {
            int idx = tid + l * 256;
            int cp = idx & 31, kk = idx >> 5;
            int gk = k0 + kk, gc = col0 + 2 * cp;
            float2 bv = make_float2(0.0f, 0.0f);
            if (gk < K && gc < Nd) bv = *(const float2*)(B + (size_t)gk * Nd + gc);
            Bs[kk][cp] = pack2(bv.x, bv.y);
        }
        __syncthreads();
#pragma unroll
        for (int kk = 0; kk < 16; kk++) {
            ulonglong2 bb = *(const ulonglong2*)&Bs[kk][2 * tx];
#pragma unroll
            for (int i = 0; i < 4; i++) {
                ulonglong2 aa = *(const ulonglong2*)&As[kk][ty * 8 + 2 * i];
                ffma2(acc[2 * i][0],     aa.x, bb.x);
                ffma2(acc[2 * i][1],     aa.x, bb.y);
                ffma2(acc[2 * i + 1][0], aa.y, bb.x);
                ffma2(acc[2 * i + 1][1], aa.y, bb.y);
            }
        }
        __syncthreads();
    }

    int colb = col0 + tx * 4;
    bool fullvec = (row0 + 127 < M) && (col0 + 63 < Nd);
    if (fullvec) {
        float4 bb;
        if (OUT_RELU) bb = *(const float4*)(bout + colb);
#pragma unroll
        for (int i = 0; i < 8; i++) {
            int row = row0 + ty * 8 + i;
            float4 v;
            unpack2(acc[i][0], v.x, v.y);
            unpack2(acc[i][1], v.z, v.w);
            if (OUT_RELU) {
                v.x = fmaxf(v.x + bb.x, 0.f); v.y = fmaxf(v.y + bb.y, 0.f);
                v.z = fmaxf(v.z + bb.z, 0.f); v.w = fmaxf(v.w + bb.w, 0.f);
            }
            if (OUT_SCALE) {
                float s = dinv[row];
                v.x *= s; v.y *= s; v.z *= s; v.w *= s;
            }
            *(float4*)(C + (size_t)row * Nd + colb) = v;
        }
    } else {
#pragma unroll
        for (int i = 0; i < 8; i++) {
            int row = row0 + ty * 8 + i;
            if (row >= M) continue;
            float vv[4];
            unpack2(acc[i][0], vv[0], vv[1]);
            unpack2(acc[i][1], vv[2], vv[3]);
            float s = OUT_SCALE ? dinv[row] : 1.0f;
#pragma unroll
            for (int j = 0; j < 4; j++) {
                int col = colb + j;
                if (col >= Nd) continue;
                float v = vv[j];
                if (OUT_RELU) v = fmaxf(v + bout[col], 0.0f);
                if (OUT_SCALE) v *= s;
                C[(size_t)row * Nd + col] = v;
            }
        }
    }
}

// ---------------------------------------------------------------------------
// Final fused head: mu/logstd GEMV (42 -> 21 each), reparam, log_softmax.
// ---------------------------------------------------------------------------
__global__ void __launch_bounds__(128)
k_final(const float* __restrict__ p5,
        const float* __restrict__ Wmu, const float* __restrict__ bmu,
        const float* __restrict__ Wls, const float* __restrict__ bls,
        const float* __restrict__ eps, float* __restrict__ out) {
    __shared__ float sWmu[42 * 21];
    __shared__ float sWls[42 * 21];
    __shared__ float sbmu[21];
    __shared__ float sbls[21];
    for (int i = threadIdx.x; i < 42 * 21; i += blockDim.x) {
        sWmu[i] = Wmu[i];
        sWls[i] = Wls[i];
    }
    if (threadIdx.x < 21) {
        sbmu[threadIdx.x] = bmu[threadIdx.x];
        sbls[threadIdx.x] = bls[threadIdx.x];
    }
    __syncthreads();

    int n = blockIdx.x * blockDim.x + threadIdx.x;
    if (n >= NN) return;

    float xr[42];
#pragma unroll
    for (int i = 0; i < 42; i++) xr[i] = p5[(size_t)n * 42 + i];

    float z[21];
#pragma unroll
    for (int j = 0; j < 21; j++) {
        float mu = sbmu[j];
        float ls = sbls[j];
#pragma unroll
        for (int i = 0; i < 42; i++) {
            mu += xr[i] * sWmu[i * 21 + j];
            ls += xr[i] * sWls[i * 21 + j];
        }
        ls = fminf(ls, 10.0f);
        z[j] = mu + eps[(size_t)n * 21 + j] * expf(ls);
    }
    float m = z[0];
#pragma unroll
    for (int j = 1; j < 21; j++) m = fmaxf(m, z[j]);
    float s = 0.0f;
#pragma unroll
    for (int j = 0; j < 21; j++) s += expf(z[j] - m);
    float lse = m + logf(s);
#pragma unroll
    for (int j = 0; j < 21; j++) out[(size_t)n * 21 + j] = z[j] - lse;
}

// ---------------------------------------------------------------------------
static inline int cdiv(long a, long b) { return (int)((a + b - 1) / b); }

extern "C" void kernel_launch(void* const* d_in, const int* in_sizes, int n_in,
                              void* d_out, int out_size) {
    const float* x    = (const float*)d_in[0];
    const int*   ei   = (const int*)  d_in[1];
    const float* eps  = (const float*)d_in[2];
    const float* W1   = (const float*)d_in[3];
    const float* b1   = (const float*)d_in[4];
    const float* W2   = (const float*)d_in[5];
    const float* b2   = (const float*)d_in[6];
    const float* W3   = (const float*)d_in[7];
    const float* b3   = (const float*)d_in[8];
    const float* W4   = (const float*)d_in[9];
    const float* b4   = (const float*)d_in[10];
    const float* Wmu  = (const float*)d_in[11];
    const float* bmu  = (const float*)d_in[12];
    const float* Wls  = (const float*)d_in[13];
    const float* bls  = (const float*)d_in[14];
    float* out = (float*)d_out;

    float *dinv, *xx, *p0, *a1, *tt2, *p2, *tt3, *p3, *tt4, *a4s, *p5;
    int *cnt, *cur, *off, *adj, *part;
    cudaGetSymbolAddress((void**)&dinv, g_dinv);
    cudaGetSymbolAddress((void**)&xx,  g_xx);
    cudaGetSymbolAddress((void**)&p0,  g_p0);
    cudaGetSymbolAddress((void**)&a1,  g_a1);
    cudaGetSymbolAddress((void**)&tt2, g_tt2);
    cudaGetSymbolAddress((void**)&p2,  g_p2);
    cudaGetSymbolAddress((void**)&tt3, g_tt3);
    cudaGetSymbolAddress((void**)&p3,  g_p3);
    cudaGetSymbolAddress((void**)&tt4, g_tt4);
    cudaGetSymbolAddress((void**)&a4s, g_a4s);
    cudaGetSymbolAddress((void**)&p5,  g_p5);
    cudaGetSymbolAddress((void**)&cnt, g_cnt);
    cudaGetSymbolAddress((void**)&cur, g_cur);
    cudaGetSymbolAddress((void**)&off, g_off);
    cudaGetSymbolAddress((void**)&adj, g_adj);
    cudaGetSymbolAddress((void**)&part, g_part);

    const int* src = ei;
    const int* dst = ei + EE;

    // ---- CSR build + normalization ----
    k_zero2<<<cdiv(NN, 256), 256>>>(cnt, cur);
    k_count<<<cdiv(EE, 256), 256>>>(dst, cnt);
    k_scan1<<<NPART, 1024>>>(cnt, off, part, dinv);
    k_scan2<<<1, 32>>>(part, off);
    k_scan3<<<NPART, 1024>>>(off, part);
    k_fill<<<cdiv(EE, 256), 256>>>(src, dst, off, cur, adj);

    // ---- conv1: aggregate x (D=36), then GEMM 35->336 (+b1, relu) ----
    k_pad_scale<<<cdiv((long)NN * 36, 256), 256>>>(x, dinv, xx);
    k_agg<36, 4, false><<<cdiv(NN, 28), 252>>>(off, adj, dinv, xx, nullptr, p0);
    k_gemm2<false, true, false><<<dim3(cdiv(NN, 128), 6), 256>>>(
        p0, 36, nullptr, W1, b1, a1, nullptr, NN, 35, 336);

    // ---- conv2: GEMM 336->168 (scaled out), aggregate ----
    k_gemm2<false, false, true><<<dim3(cdiv(NN, 128), 3), 256>>>(
        a1, 336, nullptr, W2, nullptr, tt2, dinv, NN, 336, 168);
    k_agg<168, 4, false><<<cdiv(NN, 6), 252>>>(off, adj, dinv, tt2, nullptr, p2);

    // ---- conv3: in = relu(p2+b2), 168->84, scaled out ----
    k_gemm2<true, false, true><<<dim3(cdiv(NN, 128), 2), 256>>>(
        p2, 168, b2, W3, nullptr, tt3, dinv, NN, 168, 84);
    k_agg<84, 4, false><<<cdiv(NN, 12), 252>>>(off, adj, dinv, tt3, nullptr, p3);

    // ---- conv4: in = relu(p3+b3), 84->42, scaled out;
    //      agg fuses relu+bias+rescale: a4s = dinv*relu(dinv*sum + b4) ----
    k_gemm2<true, false, true><<<dim3(cdiv(NN, 128), 1), 256>>>(
        p3, 84, b3, W4, nullptr, tt4, dinv, NN, 84, 42);
    k_agg<42, 2, true><<<cdiv(NN, 12), 252>>>(off, adj, dinv, tt4, b4, a4s);

    // ---- shared head propagation ----
    k_agg<42, 2, false><<<cdiv(NN, 12), 252>>>(off, adj, dinv, a4s, nullptr, p5);

    // ---- fused heads + reparam + log_softmax ----
    k_final<<<cdiv(NN, 128), 128>>>(p5, Wmu, bmu, Wls, bls, eps, out);
}

// round 7
// speedup vs baseline: 1.1714x; 1.0195x over previous
#include <cuda_runtime.h>
#include <cstdint>

#define NN 100000
#define EE 1600000
#define NPART 98   // ceil(NN/1024)

// ---------------------------------------------------------------------------
// Static device scratch
// ---------------------------------------------------------------------------
__device__ __align__(256) float g_dinv[NN];
__device__ __align__(256) float g_xx [NN * 36];     // dinv * padded x
__device__ __align__(256) float g_p0 [NN * 36];     // agg
__device__ __align__(256) float g_a1 [NN * 336];    // relu(conv1)
__device__ __align__(256) float g_tt2[NN * 168];    // dinv * (a1@W2)
__device__ __align__(256) float g_p2 [NN * 168];
__device__ __align__(256) float g_tt3[NN * 84];
__device__ __align__(256) float g_p3 [NN * 84];
__device__ __align__(256) float g_tt4[NN * 42];
__device__ __align__(256) float g_a4s[NN * 42];     // dinv * relu(p4+b4), fused in agg
__device__ __align__(256) float g_p5 [NN * 42];

__device__ __align__(256) int g_cnt[NN];
__device__ __align__(256) int g_cur[NN];
__device__ __align__(256) int g_off[NN + 1];
__device__ __align__(256) int g_adj[EE];
__device__ __align__(256) int g_part[NPART];

// ---------------------------------------------------------------------------
// Packed f32x2 helpers (Blackwell FFMA2 — only via PTX)
// ---------------------------------------------------------------------------
__device__ __forceinline__ uint64_t pack2(float lo, float hi) {
    uint64_t r;
    asm("mov.b64 %0, {%1, %2};" : "=l"(r) : "f"(lo), "f"(hi));
    return r;
}
__device__ __forceinline__ void unpack2(uint64_t v, float& lo, float& hi) {
    asm("mov.b64 {%0, %1}, %2;" : "=f"(lo), "=f"(hi) : "l"(v));
}
__device__ __forceinline__ void ffma2(uint64_t& d, uint64_t a, uint64_t b) {
    asm("fma.rn.f32x2 %0, %1, %2, %3;" : "=l"(d) : "l"(a), "l"(b), "l"(d));
}

// ---------------------------------------------------------------------------
// CSR build
// ---------------------------------------------------------------------------
__global__ void k_zero2(int* cnt, int* cur) {
    int i = blockIdx.x * blockDim.x + threadIdx.x;
    if (i < NN) { cnt[i] = 0; cur[i] = 0; }
}
__global__ void k_count(const int* __restrict__ dst, int* cnt) {
    int e = blockIdx.x * blockDim.x + threadIdx.x;
    if (e < EE) atomicAdd(&cnt[dst[e]], 1);
}
// scan1 also emits dinv = rsqrt(cnt+1)
__global__ void k_scan1(const int* __restrict__ cnt, int* __restrict__ off,
                        int* __restrict__ part, float* __restrict__ dinv) {
    __shared__ int s[1024];
    int t = threadIdx.x;
    int i = blockIdx.x * 1024 + t;
    int v = (i < NN) ? cnt[i] : 0;
    if (i < NN) dinv[i] = rsqrtf((float)v + 1.0f);
    s[t] = v;
    __syncthreads();
    for (int d = 1; d < 1024; d <<= 1) {
        int u = (t >= d) ? s[t - d] : 0;
        __syncthreads();
        s[t] += u;
        __syncthreads();
    }
    if (i < NN) off[i] = s[t] - v;          // exclusive
    if (t == 1023) part[blockIdx.x] = s[1023];
}
__global__ void k_scan2(int* part, int* off) {
    if (threadIdx.x == 0 && blockIdx.x == 0) {
        int run = 0;
        for (int p = 0; p < NPART; p++) { int c = part[p]; part[p] = run; run += c; }
        off[NN] = EE;
    }
}
__global__ void k_scan3(int* __restrict__ off, const int* __restrict__ part) {
    int i = blockIdx.x * 1024 + threadIdx.x;
    if (i < NN) off[i] += part[blockIdx.x];
}
__global__ void k_fill(const int* __restrict__ src, const int* __restrict__ dst,
                       const int* __restrict__ off, int* cur, int* __restrict__ adj) {
    int e = blockIdx.x * blockDim.x + threadIdx.x;
    if (e >= EE) return;
    int d = dst[e];
    int p = off[d] + atomicAdd(&cur[d], 1);
    adj[p] = src[e];
}

// ---------------------------------------------------------------------------
// Elementwise: xx = dinv[n] * pad(x)   (35 -> 36)
// ---------------------------------------------------------------------------
__global__ void k_pad_scale(const float* __restrict__ x, const float* __restrict__ dinv,
                            float* __restrict__ xx) {
    int i = blockIdx.x * blockDim.x + threadIdx.x;
    if (i >= NN * 36) return;
    int n = i / 36, c = i - n * 36;
    float v = (c < 35) ? x[(size_t)n * 35 + c] : 0.0f;
    xx[i] = v * dinv[n];
}

// ---------------------------------------------------------------------------
// CSR gather aggregation, 2-way unrolled (MLP=2):
//   base: p[d] = dinv[d] * (tt[d] + sum_{s in N(d)} tt[s])
//   RBS:  p[d] = dinv[d] * relu(base + bias[c])   (fused relu+bias+rescale)
// ---------------------------------------------------------------------------
template <int D, int VEC, bool RBS>
__global__ void __launch_bounds__(252)
k_agg(const int* __restrict__ off, const int* __restrict__ adj,
      const float* __restrict__ dinv, const float* __restrict__ tt,
      const float* __restrict__ bias, float* __restrict__ p) {
    constexpr int G = D / VEC;
    constexpr int NPB = 252 / G;
    int g = threadIdx.x / G;
    int c = (threadIdx.x - g * G) * VEC;
    int node = blockIdx.x * NPB + g;
    if (node >= NN) return;
    int ib = off[node], ie = off[node + 1];
    float sc = dinv[node];
    if (VEC == 4) {
        float4 acc = *(const float4*)(tt + (size_t)node * D + c);
        float4 acc2 = make_float4(0.f, 0.f, 0.f, 0.f);
        int i = ib;
        for (; i + 2 <= ie; i += 2) {
            int s0 = adj[i], s1 = adj[i + 1];
            float4 v0 = *(const float4*)(tt + (size_t)s0 * D + c);
            float4 v1 = *(const float4*)(tt + (size_t)s1 * D + c);
            acc.x += v0.x; acc.y += v0.y; acc.z += v0.z; acc.w += v0.w;
            acc2.x += v1.x; acc2.y += v1.y; acc2.z += v1.z; acc2.w += v1.w;
        }
        if (i < ie) {
            int s0 = adj[i];
            float4 v0 = *(const float4*)(tt + (size_t)s0 * D + c);
            acc.x += v0.x; acc.y += v0.y; acc.z += v0.z; acc.w += v0.w;
        }
        acc.x = (acc.x + acc2.x) * sc; acc.y = (acc.y + acc2.y) * sc;
        acc.z = (acc.z + acc2.z) * sc; acc.w = (acc.w + acc2.w) * sc;
        if (RBS) {
            acc.x = fmaxf(acc.x + bias[c + 0], 0.f) * sc;
            acc.y = fmaxf(acc.y + bias[c + 1], 0.f) * sc;
            acc.z = fmaxf(acc.z + bias[c + 2], 0.f) * sc;
            acc.w = fmaxf(acc.w + bias[c + 3], 0.f) * sc;
        }
        *(float4*)(p + (size_t)node * D + c) = acc;
    } else {
        float2 acc = *(const float2*)(tt + (size_t)node * D + c);
        float2 acc2 = make_float2(0.f, 0.f);
        int i = ib;
        for (; i + 2 <= ie; i += 2) {
            int s0 = adj[i], s1 = adj[i + 1];
            float2 v0 = *(const float2*)(tt + (size_t)s0 * D + c);
            float2 v1 = *(const float2*)(tt + (size_t)s1 * D + c);
            acc.x += v0.x; acc.y += v0.y;
            acc2.x += v1.x; acc2.y += v1.y;
        }
        if (i < ie) {
            int s0 = adj[i];
            float2 v0 = *(const float2*)(tt + (size_t)s0 * D + c);
            acc.x += v0.x; acc.y += v0.y;
        }
        acc.x = (acc.x + acc2.x) * sc;
        acc.y = (acc.y + acc2.y) * sc;
        if (RBS) {
            acc.x = fmaxf(acc.x + bias[c + 0], 0.f) * sc;
            acc.y = fmaxf(acc.y + bias[c + 1], 0.f) * sc;
        }
        *(float2*)(p + (size_t)node * D + c) = acc;
    }
}

// ---------------------------------------------------------------------------
// f32x2 GEMM, 128x64 tile, 256 threads, 8x4 microtile, DOUBLE-BUFFERED smem.
// One __syncthreads per k-tile; tile t+1's LDGs issue before tile t's FFMA2s
// so global latency hides under compute. Buffer strides even -> ulonglong2
// smem reads stay 16B-aligned.
// ---------------------------------------------------------------------------
template <bool IN_RELU, bool OUT_RELU, bool OUT_SCALE>
__global__ void __launch_bounds__(256)
k_gemm2(const float* __restrict__ A, int lda, const float* __restrict__ binA,
        const float* __restrict__ B, const float* __restrict__ bout,
        float* __restrict__ C, const float* __restrict__ dinv,
        int M, int K, int Nd) {
    __shared__ uint64_t As[2][16][130];
    __shared__ uint64_t Bs[2][16][34];

    int tid = threadIdx.x;
    int tx = tid & 15;
    int ty = tid >> 4;
    int row0 = blockIdx.x * 128;
    int col0 = blockIdx.y * 64;

    uint64_t acc[8][2];
#pragma unroll
    for (int i = 0; i < 8; i++) { acc[i][0] = 0ull; acc[i][1] = 0ull; }

    auto load_tile = [&](int k0, int buf) {
#pragma unroll
        for (int l = 0; l < 8; l++) {
            int idx = tid + l * 256;
            int kk = idx & 15, rr = idx >> 4;
            int grow = row0 + rr, gk = k0 + kk;
            float a = 0.0f;
            if (grow < M && gk < K) {
                a = A[(size_t)grow * lda + gk];
                if (IN_RELU) a = fmaxf(a + binA[gk], 0.0f);
            }
            As[buf][kk][rr] = pack2(a, a);
        }
#pragma unroll
        for (int l = 0; l < 2; l++) {
            int idx = tid + l * 256;
            int cp = idx & 31, kk = idx >> 5;
            int gk = k0 + kk, gc = col0 + 2 * cp;
            float2 bv = make_float2(0.0f, 0.0f);
            if (gk < K && gc < Nd) bv = *(const float2*)(B + (size_t)gk * Nd + gc);
            Bs[buf][kk][cp] = pack2(bv.x, bv.y);
        }
    };

    int nt = (K + 15) >> 4;
    load_tile(0, 0);
    __syncthreads();

    for (int t = 0; t < nt; t++) {
        int buf = t & 1;
        if (t + 1 < nt) load_tile((t + 1) * 16, buf ^ 1);
#pragma unroll
        for (int kk = 0; kk < 16; kk++) {
            ulonglong2 bb = *(const ulonglong2*)&Bs[buf][kk][2 * tx];
#pragma unroll
            for (int i = 0; i < 4; i++) {
                ulonglong2 aa = *(const ulonglong2*)&As[buf][kk][ty * 8 + 2 * i];
                ffma2(acc[2 * i][0],     aa.x, bb.x);
                ffma2(acc[2 * i][1],     aa.x, bb.y);
                ffma2(acc[2 * i + 1][0], aa.y, bb.x);
                ffma2(acc[2 * i + 1][1], aa.y, bb.y);
            }
        }
        __syncthreads();
    }

    int colb = col0 + tx * 4;
    bool fullvec = (row0 + 127 < M) && (col0 + 63 < Nd);
    if (fullvec) {
        float4 bb;
        if (OUT_RELU) bb = *(const float4*)(bout + colb);
#pragma unroll
        for (int i = 0; i < 8; i++) {
            int row = row0 + ty * 8 + i;
            float4 v;
            unpack2(acc[i][0], v.x, v.y);
            unpack2(acc[i][1], v.z, v.w);
            if (OUT_RELU) {
                v.x = fmaxf(v.x + bb.x, 0.f); v.y = fmaxf(v.y + bb.y, 0.f);
                v.z = fmaxf(v.z + bb.z, 0.f); v.w = fmaxf(v.w + bb.w, 0.f);
            }
            if (OUT_SCALE) {
                float s = dinv[row];
                v.x *= s; v.y *= s; v.z *= s; v.w *= s;
            }
            *(float4*)(C + (size_t)row * Nd + colb) = v;
        }
    } else {
#pragma unroll
        for (int i = 0; i < 8; i++) {
            int row = row0 + ty * 8 + i;
            if (row >= M) continue;
            float vv[4];
            unpack2(acc[i][0], vv[0], vv[1]);
            unpack2(acc[i][1], vv[2], vv[3]);
            float s = OUT_SCALE ? dinv[row] : 1.0f;
#pragma unroll
            for (int j = 0; j < 4; j++) {
                int col = colb + j;
                if (col >= Nd) continue;
                float v = vv[j];
                if (OUT_RELU) v = fmaxf(v + bout[col], 0.0f);
                if (OUT_SCALE) v *= s;
                C[(size_t)row * Nd + col] = v;
            }
        }
    }
}

// ---------------------------------------------------------------------------
// Final fused head: mu/logstd GEMV (42 -> 21 each), reparam, log_softmax.
// ---------------------------------------------------------------------------
__global__ void __launch_bounds__(128)
k_final(const float* __restrict__ p5,
        const float* __restrict__ Wmu, const float* __restrict__ bmu,
        const float* __restrict__ Wls, const float* __restrict__ bls,
        const float* __restrict__ eps, float* __restrict__ out) {
    __shared__ float sWmu[42 * 21];
    __shared__ float sWls[42 * 21];
    __shared__ float sbmu[21];
    __shared__ float sbls[21];
    for (int i = threadIdx.x; i < 42 * 21; i += blockDim.x) {
        sWmu[i] = Wmu[i];
        sWls[i] = Wls[i];
    }
    if (threadIdx.x < 21) {
        sbmu[threadIdx.x] = bmu[threadIdx.x];
        sbls[threadIdx.x] = bls[threadIdx.x];
    }
    __syncthreads();

    int n = blockIdx.x * blockDim.x + threadIdx.x;
    if (n >= NN) return;

    float xr[42];
#pragma unroll
    for (int i = 0; i < 42; i++) xr[i] = p5[(size_t)n * 42 + i];

    float z[21];
#pragma unroll
    for (int j = 0; j < 21; j++) {
        float mu = sbmu[j];
        float ls = sbls[j];
#pragma unroll
        for (int i = 0; i < 42; i++) {
            mu += xr[i] * sWmu[i * 21 + j];
            ls += xr[i] * sWls[i * 21 + j];
        }
        ls = fminf(ls, 10.0f);
        z[j] = mu + eps[(size_t)n * 21 + j] * expf(ls);
    }
    float m = z[0];
#pragma unroll
    for (int j = 1; j < 21; j++) m = fmaxf(m, z[j]);
    float s = 0.0f;
#pragma unroll
    for (int j = 0; j < 21; j++) s += expf(z[j] - m);
    float lse = m + logf(s);
#pragma unroll
    for (int j = 0; j < 21; j++) out[(size_t)n * 21 + j] = z[j] - lse;
}

// ---------------------------------------------------------------------------
static inline int cdiv(long a, long b) { return (int)((a + b - 1) / b); }

extern "C" void kernel_launch(void* const* d_in, const int* in_sizes, int n_in,
                              void* d_out, int out_size) {
    const float* x    = (const float*)d_in[0];
    const int*   ei   = (const int*)  d_in[1];
    const float* eps  = (const float*)d_in[2];
    const float* W1   = (const float*)d_in[3];
    const float* b1   = (const float*)d_in[4];
    const float* W2   = (const float*)d_in[5];
    const float* b2   = (const float*)d_in[6];
    const float* W3   = (const float*)d_in[7];
    const float* b3   = (const float*)d_in[8];
    const float* W4   = (const float*)d_in[9];
    const float* b4   = (const float*)d_in[10];
    const float* Wmu  = (const float*)d_in[11];
    const float* bmu  = (const float*)d_in[12];
    const float* Wls  = (const float*)d_in[13];
    const float* bls  = (const float*)d_in[14];
    float* out = (float*)d_out;

    float *dinv, *xx, *p0, *a1, *tt2, *p2, *tt3, *p3, *tt4, *a4s, *p5;
    int *cnt, *cur, *off, *adj, *part;
    cudaGetSymbolAddress((void**)&dinv, g_dinv);
    cudaGetSymbolAddress((void**)&xx,  g_xx);
    cudaGetSymbolAddress((void**)&p0,  g_p0);
    cudaGetSymbolAddress((void**)&a1,  g_a1);
    cudaGetSymbolAddress((void**)&tt2, g_tt2);
    cudaGetSymbolAddress((void**)&p2,  g_p2);
    cudaGetSymbolAddress((void**)&tt3, g_tt3);
    cudaGetSymbolAddress((void**)&p3,  g_p3);
    cudaGetSymbolAddress((void**)&tt4, g_tt4);
    cudaGetSymbolAddress((void**)&a4s, g_a4s);
    cudaGetSymbolAddress((void**)&p5,  g_p5);
    cudaGetSymbolAddress((void**)&cnt, g_cnt);
    cudaGetSymbolAddress((void**)&cur, g_cur);
    cudaGetSymbolAddress((void**)&off, g_off);
    cudaGetSymbolAddress((void**)&adj, g_adj);
    cudaGetSymbolAddress((void**)&part, g_part);

    const int* src = ei;
    const int* dst = ei + EE;

    // ---- CSR build + normalization ----
    k_zero2<<<cdiv(NN, 256), 256>>>(cnt, cur);
    k_count<<<cdiv(EE, 256), 256>>>(dst, cnt);
    k_scan1<<<NPART, 1024>>>(cnt, off, part, dinv);
    k_scan2<<<1, 32>>>(part, off);
    k_scan3<<<NPART, 1024>>>(off, part);
    k_fill<<<cdiv(EE, 256), 256>>>(src, dst, off, cur, adj);

    // ---- conv1: aggregate x (D=36), then GEMM 35->336 (+b1, relu) ----
    k_pad_scale<<<cdiv((long)NN * 36, 256), 256>>>(x, dinv, xx);
    k_agg<36, 4, false><<<cdiv(NN, 28), 252>>>(off, adj, dinv, xx, nullptr, p0);
    k_gemm2<false, true, false><<<dim3(cdiv(NN, 128), 6), 256>>>(
        p0, 36, nullptr, W1, b1, a1, nullptr, NN, 35, 336);

    // ---- conv2: GEMM 336->168 (scaled out), aggregate ----
    k_gemm2<false, false, true><<<dim3(cdiv(NN, 128), 3), 256>>>(
        a1, 336, nullptr, W2, nullptr, tt2, dinv, NN, 336, 168);
    k_agg<168, 4, false><<<cdiv(NN, 6), 252>>>(off, adj, dinv, tt2, nullptr, p2);

    // ---- conv3: in = relu(p2+b2), 168->84, scaled out ----
    k_gemm2<true, false, true><<<dim3(cdiv(NN, 128), 2), 256>>>(
        p2, 168, b2, W3, nullptr, tt3, dinv, NN, 168, 84);
    k_agg<84, 4, false><<<cdiv(NN, 12), 252>>>(off, adj, dinv, tt3, nullptr, p3);

    // ---- conv4: in = relu(p3+b3), 84->42, scaled out;
    //      agg fuses relu+bias+rescale: a4s = dinv*relu(dinv*sum + b4) ----
    k_gemm2<true, false, true><<<dim3(cdiv(NN, 128), 1), 256>>>(
        p3, 84, b3, W4, nullptr, tt4, dinv, NN, 84, 42);
    k_agg<42, 2, true><<<cdiv(NN, 12), 252>>>(off, adj, dinv, tt4, b4, a4s);

    // ---- shared head propagation ----
    k_agg<42, 2, false><<<cdiv(NN, 12), 252>>>(off, adj, dinv, a4s, nullptr, p5);

    // ---- fused heads + reparam + log_softmax ----
    k_final<<<cdiv(NN, 128), 128>>>(p5, Wmu, bmu, Wls, bls, eps, out);
}